// round 16
// baseline (speedup 1.0000x reference)
#include <cuda_runtime.h>
#include <cuda_fp16.h>
#include <math.h>
#include <stdint.h>

// ===========================================================================
// Problem constants (fixed shapes)
// ===========================================================================
#define NN     50000          // nodes
#define NNP    50048          // padded to 128
#define IND    3703           // input dim
#define INDP   3712           // padded to 64
#define HID    500
#define HSTR   512            // padded hidden
#define EMAX   1000000

// ===========================================================================
// Device scratch (static globals; no dynamic allocation).
// h/x pad rows+cols rely on static zero-init and are never written.
// ===========================================================================
__device__ __half g_xh[(size_t)NNP * INDP];
__device__ __half g_w1[HSTR * INDP];
__device__ __half g_w2b[HSTR * HSTR];
__device__ __half g_h[(size_t)NNP * HSTR];
__device__ __half g_z[(size_t)NNP * HSTR];   // GEMM output (fp16)
__device__ float g_s1[(size_t)NNP * 8];      // layer-3 per-node logits (pre-agg)

__device__ int   g_cnt[NNP];
__device__ int   g_part[NNP];
__device__ int   g_aux[256];
__device__ int   g_ptr[NN + 1];
__device__ int   g_wp[NNP];
__device__ int   g_csrc[EMAX];
__device__ float g_cw[EMAX];

// ===========================================================================
// Helpers
// ===========================================================================
__device__ __forceinline__ uint32_t smem_to_u32(const void* p) {
    uint32_t a;
    asm("{ .reg .u64 t; cvta.to.shared.u64 t, %1; cvt.u32.u64 %0, t; }"
        : "=r"(a) : "l"(p));
    return a;
}
__device__ __forceinline__ void ldsm4(uint32_t& r0, uint32_t& r1,
                                      uint32_t& r2, uint32_t& r3, uint32_t addr) {
    asm volatile("ldmatrix.sync.aligned.m8n8.x4.shared.b16 {%0,%1,%2,%3}, [%4];"
        : "=r"(r0), "=r"(r1), "=r"(r2), "=r"(r3) : "r"(addr));
}
__device__ __forceinline__ void mma16816(float* c, const uint32_t* a,
                                         uint32_t b0, uint32_t b1) {
    asm volatile("mma.sync.aligned.m16n8k16.row.col.f32.f16.f16.f32 "
        "{%0,%1,%2,%3}, {%4,%5,%6,%7}, {%8,%9}, {%0,%1,%2,%3};"
        : "+f"(c[0]), "+f"(c[1]), "+f"(c[2]), "+f"(c[3])
        : "r"(a[0]), "r"(a[1]), "r"(a[2]), "r"(a[3]), "r"(b0), "r"(b1));
}
__device__ __forceinline__ void cp16(uint32_t soff, const void* g) {
    asm volatile("cp.async.cg.shared.global [%0], [%1], 16;" :: "r"(soff), "l"(g));
}
__device__ __forceinline__ uint32_t pkh(__half a, __half b) {
    return (uint32_t)__half_as_ushort(a) | ((uint32_t)__half_as_ushort(b) << 16);
}

// ===========================================================================
// X -> fp16 for rows [roff, roff+rcnt)
// ===========================================================================
#define XCHUNKS (INDP / 8)   // 464
__global__ __launch_bounds__(256)
void split_x_kernel(const float* __restrict__ x, __half* __restrict__ xh,
                    int roff, int rcnt)
{
    int idx = blockIdx.x * 256 + threadIdx.x;
    int total = rcnt * XCHUNKS;
    if (idx >= total) return;
    int row = roff + idx / XCHUNKS;
    int cb  = (idx % XCHUNKS) * 8;
    const float* px = x + (size_t)row * IND;
    __half hh[8];
#pragma unroll
    for (int j = 0; j < 8; j++) {
        int c = cb + j;
        hh[j] = __float2half_rn((c < IND) ? px[c] : 0.f);
    }
    size_t off = (size_t)row * INDP + cb;
    uint4 uh;
    uh.x = pkh(hh[0], hh[1]); uh.y = pkh(hh[2], hh[3]);
    uh.z = pkh(hh[4], hh[5]); uh.w = pkh(hh[6], hh[7]);
    *(uint4*)(xh + off) = uh;
}

// ===========================================================================
// Weight prep (coalesced transpose): w [K x N] fp32 -> fp16 [NP][KP]
// ===========================================================================
__global__ __launch_bounds__(256)
void prep_w_kernel(const float* __restrict__ w, __half* __restrict__ dh,
                   int K, int N, int KP, int NP)
{
    __shared__ float t[32][33];
    int kb = blockIdx.x * 32;
    int nb = blockIdx.y * 32;
    int tx = threadIdx.x & 31;
    int ty = threadIdx.x >> 5;     // 0..7
#pragma unroll
    for (int i = ty; i < 32; i += 8) {
        int k = kb + i, n = nb + tx;
        t[i][tx] = (k < K && n < N) ? w[(size_t)k * N + n] : 0.f;
    }
    __syncthreads();
#pragma unroll
    for (int i = ty; i < 32; i += 8) {
        int n = nb + i, k = kb + tx;
        if (n < NP && k < KP)
            dh[(size_t)n * KP + k] = __float2half_rn(t[tx][i]);
    }
}

// ===========================================================================
// CSR build
// ===========================================================================
__global__ void cnt_zero_kernel(int* __restrict__ cnt) {
    int i = blockIdx.x * 256 + threadIdx.x;
    if (i < NNP) cnt[i] = 0;
}
__global__ void hist_kernel(const int* __restrict__ ed, int* __restrict__ cnt, int E) {
    int e = blockIdx.x * 256 + threadIdx.x;
    if (e < E) atomicAdd(&cnt[ed[e]], 1);
}
__global__ void scan1_kernel(const int* __restrict__ cnt, int* __restrict__ part,
                             int* __restrict__ aux, int n)
{
    __shared__ int s[256];
    int tid = threadIdx.x;
    int g = blockIdx.x * 256 + tid;
    int v = (g < n) ? cnt[g] : 0;
    s[tid] = v;
    __syncthreads();
#pragma unroll
    for (int o = 1; o < 256; o <<= 1) {
        int t = (tid >= o) ? s[tid - o] : 0;
        __syncthreads();
        s[tid] += t;
        __syncthreads();
    }
    if (g < n) part[g] = s[tid] - v;
    if (tid == 255) aux[blockIdx.x] = s[tid];
}
__global__ void scan2_kernel(int* __restrict__ aux, int nb)
{
    __shared__ int s[256];
    int tid = threadIdx.x;
    int v = (tid < nb) ? aux[tid] : 0;
    s[tid] = v;
    __syncthreads();
#pragma unroll
    for (int o = 1; o < 256; o <<= 1) {
        int t = (tid >= o) ? s[tid - o] : 0;
        __syncthreads();
        s[tid] += t;
        __syncthreads();
    }
    if (tid < nb) aux[tid] = s[tid] - v;   // exclusive
}
__global__ void scan3_kernel(const int* __restrict__ part, const int* __restrict__ aux,
                             int* __restrict__ ptr, int* __restrict__ wp, int n, int E)
{
    int g = blockIdx.x * 256 + threadIdx.x;
    if (g < n) {
        int v = part[g] + aux[g >> 8];
        ptr[g] = v;
        wp[g] = v;
    }
    if (g == 0) ptr[n] = E;
}
__global__ void fill_kernel(const int* __restrict__ es, const int* __restrict__ ed,
                            const float* __restrict__ ew, int* __restrict__ wp,
                            int* __restrict__ csrc, float* __restrict__ cw, int E)
{
    int e = blockIdx.x * 256 + threadIdx.x;
    if (e >= E) return;
    int d = ed[e];
    int p = atomicAdd(&wp[d], 1);
    csrc[p] = es[e];
    cw[p] = ew[e];
}

// ===========================================================================
// HMMA GEMM (R11-proven mainloop): C[M x 512] = A[M x K] @ B^T[512 x K],
// fp16 operands, fp32 accum. BK=64 per stage as TWO BK=32 tile-pairs
// [A0|A1|B0|B1]; 2-stage cp.async pipeline; 256 threads, warp tile 64x32.
// m_off: y-block offset for M-sliced launches.
// ===========================================================================
#define STG 32768   // bytes per stage: 4 sub-tiles x 8KB

__global__ __launch_bounds__(256)
void gemm_hmma_kernel(const __half* __restrict__ Ah, int lda,
                      const __half* __restrict__ Bh, int ldb,
                      __half* __restrict__ C, int ldc, int nkc, int m_off)
{
    extern __shared__ char smem[];
    const uint32_t sb = smem_to_u32(smem);
    const int tid  = threadIdx.x;
    const int lane = tid & 31;
    const int wid  = tid >> 5;
    const int m0 = (blockIdx.y + m_off) * 128;
    const int n0 = blockIdx.x * 128;
    const int wm = (wid >> 2) * 64;
    const int wn = (wid & 3) * 32;

    float acc[4][4][4];
#pragma unroll
    for (int i = 0; i < 4; i++)
#pragma unroll
        for (int j = 0; j < 4; j++)
#pragma unroll
            for (int q = 0; q < 4; q++) acc[i][j][q] = 0.f;

    auto load_stage = [&](int kc, int s) {
        int kkbase = kc * 64;
#pragma unroll
        for (int j = 0; j < 8; j++) {
            int id  = tid + j * 256;          // 0..2047
            int p   = id >> 10;               // 0..1 : which 32-col half
            int sub = id & 1023;
            int tile = sub >> 9;              // 0=A, 1=B
            int r = (sub >> 2) & 127;
            int c = sub & 3;
            uint32_t soff = sb + s * STG + tile * 16384 + p * 8192 + r * 64
                          + ((c ^ ((r >> 1) & 3)) << 4);
            int kk = kkbase + p * 32;
            const __half* g;
            if (tile == 0) g = Ah + (size_t)(m0 + r) * lda + kk + c * 8;
            else           g = Bh + (size_t)(n0 + r) * ldb + kk + c * 8;
            cp16(soff, g);
        }
        asm volatile("cp.async.commit_group;");
    };

    load_stage(0, 0);

    for (int kc = 0; kc < nkc; kc++) {
        int s = kc & 1;
        if (kc + 1 < nkc) {
            load_stage(kc + 1, s ^ 1);
            asm volatile("cp.async.wait_group 1;");
        } else {
            asm volatile("cp.async.wait_group 0;");
        }
        __syncthreads();

#pragma unroll
        for (int p = 0; p < 2; p++) {
            uint32_t tAh = sb + s * STG + p * 8192;
            uint32_t tBh = sb + s * STG + 16384 + p * 8192;

#pragma unroll
            for (int kh = 0; kh < 2; kh++) {
                uint32_t ah[4][4], bh[2][4];
                const int rlo = lane & 15;
                const int q   = 2 * kh + (lane >> 4);
#pragma unroll
                for (int i = 0; i < 4; i++) {
                    int r = wm + i * 16 + rlo;
                    uint32_t off = r * 64 + ((q ^ ((r >> 1) & 3)) << 4);
                    ldsm4(ah[i][0], ah[i][1], ah[i][2], ah[i][3], tAh + off);
                }
#pragma unroll
                for (int j = 0; j < 2; j++) {
                    int r = wn + j * 16 + rlo;
                    uint32_t off = r * 64 + ((q ^ ((r >> 1) & 3)) << 4);
                    ldsm4(bh[j][0], bh[j][1], bh[j][2], bh[j][3], tBh + off);
                }
#pragma unroll
                for (int i = 0; i < 4; i++) {
#pragma unroll
                    for (int jj = 0; jj < 4; jj++) {
                        uint32_t b0 = bh[jj >> 1][jj & 1];
                        uint32_t b1 = bh[jj >> 1][(jj & 1) + 2];
                        mma16816(acc[i][jj], ah[i], b0, b1);
                    }
                }
            }
        }
        __syncthreads();
    }

    // epilogue: fp32 acc -> fp16 stores
#pragma unroll
    for (int i = 0; i < 4; i++) {
        int row = m0 + wm + i * 16 + (lane >> 2);
#pragma unroll
        for (int jj = 0; jj < 4; jj++) {
            int col = n0 + wn + jj * 8 + 2 * (lane & 3);
            __half2 v0 = __floats2half2_rn(acc[i][jj][0], acc[i][jj][1]);
            __half2 v1 = __floats2half2_rn(acc[i][jj][2], acc[i][jj][3]);
            *(__half2*)(C + (size_t)row * ldc + col) = v0;
            *(__half2*)(C + (size_t)(row + 8) * ldc + col) = v1;
        }
    }
}

// ===========================================================================
// Layer-1 CSR gather (R9-proven): h1 = relu(agg(z1)+b1) -> fp16.
// Thread t owns cols {t, t+128, t+256, t+384}; 2-way edge unroll.
// ===========================================================================
__global__ __launch_bounds__(128)
void gather_kernel(const __half* __restrict__ src, const int* __restrict__ ptr,
                   const int* __restrict__ cs, const float* __restrict__ cw,
                   const float* __restrict__ bias,
                   __half* __restrict__ oh)
{
    int node = blockIdx.x;
    int tid = threadIdx.x;
    int beg = ptr[node], end = ptr[node + 1];
    const int c0 = tid, c1 = tid + 128, c2 = tid + 256, c3 = tid + 384;
    float a0 = 0.f, a1 = 0.f, a2 = 0.f, a3 = 0.f;
    float e0 = 0.f, e1 = 0.f, e2 = 0.f, e3 = 0.f;
    int i = beg;
    for (; i + 1 < end; i += 2) {
        int sA = cs[i],     sB = cs[i + 1];
        float wA = cw[i],   wB = cw[i + 1];
        const __half* pA = src + (size_t)sA * HSTR;
        const __half* pB = src + (size_t)sB * HSTR;
        a0 = fmaf(wA, __half2float(pA[c0]), a0);  e0 = fmaf(wB, __half2float(pB[c0]), e0);
        a1 = fmaf(wA, __half2float(pA[c1]), a1);  e1 = fmaf(wB, __half2float(pB[c1]), e1);
        a2 = fmaf(wA, __half2float(pA[c2]), a2);  e2 = fmaf(wB, __half2float(pB[c2]), e2);
        a3 = fmaf(wA, __half2float(pA[c3]), a3);  e3 = fmaf(wB, __half2float(pB[c3]), e3);
    }
    if (i < end) {
        int s = cs[i]; float w = cw[i];
        const __half* ps = src + (size_t)s * HSTR;
        a0 = fmaf(w, __half2float(ps[c0]), a0);
        a1 = fmaf(w, __half2float(ps[c1]), a1);
        a2 = fmaf(w, __half2float(ps[c2]), a2);
        a3 = fmaf(w, __half2float(ps[c3]), a3);
    }
    a0 += e0; a1 += e1; a2 += e2; a3 += e3;
    float v0 = fmaxf(a0 + bias[c0], 0.f);
    float v1 = fmaxf(a1 + bias[c1], 0.f);
    float v2 = fmaxf(a2 + bias[c2], 0.f);
    float v3 = fmaxf(a3 + ((c3 < HID) ? bias[c3] : 0.f), 0.f);
    size_t base = (size_t)node * HSTR;
    oh[base + c0] = __float2half_rn(v0);
    oh[base + c1] = __float2half_rn(v1);
    oh[base + c2] = __float2half_rn(v2);
    oh[base + c3] = __float2half_rn(v3);
}

// ===========================================================================
// Layer-2 gather fused with W3 projection (R9-proven).
// ===========================================================================
__global__ __launch_bounds__(128)
void gather_proj_kernel(const __half* __restrict__ src, const int* __restrict__ ptr,
                        const int* __restrict__ cs, const float* __restrict__ cw,
                        const float* __restrict__ bias,
                        const float* __restrict__ w3,
                        float* __restrict__ s1)
{
    __shared__ float red[6][128];
    int node = blockIdx.x;
    int tid = threadIdx.x;
    int beg = ptr[node], end = ptr[node + 1];
    const int c0 = tid, c1 = tid + 128, c2 = tid + 256, c3 = tid + 384;
    float a0 = 0.f, a1 = 0.f, a2 = 0.f, a3 = 0.f;
    float e0 = 0.f, e1 = 0.f, e2 = 0.f, e3 = 0.f;
    int i = beg;
    for (; i + 1 < end; i += 2) {
        int sA = cs[i],     sB = cs[i + 1];
        float wA = cw[i],   wB = cw[i + 1];
        const __half* pA = src + (size_t)sA * HSTR;
        const __half* pB = src + (size_t)sB * HSTR;
        a0 = fmaf(wA, __half2float(pA[c0]), a0);  e0 = fmaf(wB, __half2float(pB[c0]), e0);
        a1 = fmaf(wA, __half2float(pA[c1]), a1);  e1 = fmaf(wB, __half2float(pB[c1]), e1);
        a2 = fmaf(wA, __half2float(pA[c2]), a2);  e2 = fmaf(wB, __half2float(pB[c2]), e2);
        a3 = fmaf(wA, __half2float(pA[c3]), a3);  e3 = fmaf(wB, __half2float(pB[c3]), e3);
    }
    if (i < end) {
        int s = cs[i]; float w = cw[i];
        const __half* ps = src + (size_t)s * HSTR;
        a0 = fmaf(w, __half2float(ps[c0]), a0);
        a1 = fmaf(w, __half2float(ps[c1]), a1);
        a2 = fmaf(w, __half2float(ps[c2]), a2);
        a3 = fmaf(w, __half2float(ps[c3]), a3);
    }
    a0 += e0; a1 += e1; a2 += e2; a3 += e3;
    float v0 = fmaxf(a0 + bias[c0], 0.f);
    float v1 = fmaxf(a1 + bias[c1], 0.f);
    float v2 = fmaxf(a2 + bias[c2], 0.f);
    float v3 = (c3 < HID) ? fmaxf(a3 + bias[c3], 0.f) : 0.f;

    float p[6] = {0.f, 0.f, 0.f, 0.f, 0.f, 0.f};
    const float* r0 = w3 + (size_t)c0 * 6;
    const float* r1 = w3 + (size_t)c1 * 6;
    const float* r2 = w3 + (size_t)c2 * 6;
#pragma unroll
    for (int j = 0; j < 6; j++) {
        float t = v0 * __ldg(&r0[j]) + v1 * __ldg(&r1[j]) + v2 * __ldg(&r2[j]);
        if (c3 < HID) t += v3 * __ldg(&w3[(size_t)c3 * 6 + j]);
        p[j] = t;
    }
#pragma unroll
    for (int j = 0; j < 6; j++) red[j][tid] = p[j];
    __syncthreads();
#pragma unroll
    for (int s = 64; s >= 1; s >>= 1) {
        if (tid < s) {
#pragma unroll
            for (int j = 0; j < 6; j++) red[j][tid] += red[j][tid + s];
        }
        __syncthreads();
    }
    if (tid < 6) s1[(size_t)node * 8 + tid] = red[tid][0];
}

// ===========================================================================
// Final fused: aggregate (CSR) + b3 + log_softmax, warp per node
// ===========================================================================
__global__ void final_kernel(const float* __restrict__ s1, const int* __restrict__ ptr,
                             const int* __restrict__ cs, const float* __restrict__ cw,
                             const float* __restrict__ b3, float* __restrict__ out, int M)
{
    int node = (blockIdx.x * blockDim.x + threadIdx.x) >> 5;
    int lane = threadIdx.x & 31;
    if (node >= M) return;
    int beg = ptr[node], end = ptr[node + 1];
    float a[6] = {0.f, 0.f, 0.f, 0.f, 0.f, 0.f};
    for (int i = beg + lane; i < end; i += 32) {
        int s = cs[i];
        float w = cw[i];
        const float* ps = s1 + (size_t)s * 8;
#pragma unroll
        for (int j = 0; j < 6; j++) a[j] = fmaf(w, ps[j], a[j]);
    }
#pragma unroll
    for (int j = 0; j < 6; j++)
#pragma unroll
        for (int off = 16; off > 0; off >>= 1)
            a[j] += __shfl_xor_sync(0xffffffffu, a[j], off);
    if (lane == 0) {
        float v[6];
#pragma unroll
        for (int j = 0; j < 6; j++) v[j] = a[j] + b3[j];
        float m = v[0];
#pragma unroll
        for (int j = 1; j < 6; j++) m = fmaxf(m, v[j]);
        float s = 0.f;
#pragma unroll
        for (int j = 0; j < 6; j++) s += __expf(v[j] - m);
        float l = logf(s) + m;
        float* po = out + (size_t)node * 6;
#pragma unroll
        for (int j = 0; j < 6; j++) po[j] = v[j] - l;
    }
}

// ===========================================================================
// Launch. Streams:
//   main:  split_x slices (DRAM-bound) -> join -> gather1 -> GEMM2 -> ...
//   sg:    GEMM1 M-slices, each gated on its split_x slice event
//   s2:    CSR build chain
//   s3:    prep_w1 / prep_w2
// Streams/events cached; identical deterministic work each call.
// ===========================================================================
#define NSLICE 4

extern "C" void kernel_launch(void* const* d_in, const int* in_sizes, int n_in,
                              void* d_out, int out_size)
{
    const float* x   = (const float*)d_in[0];
    const float* w1  = (const float*)d_in[1];
    const float* b1  = (const float*)d_in[2];
    const float* w2  = (const float*)d_in[3];
    const float* b2  = (const float*)d_in[4];
    const float* w3  = (const float*)d_in[5];
    const float* b3  = (const float*)d_in[6];
    const float* ew  = (const float*)d_in[7];
    const int*   es  = (const int*)d_in[8];
    const int*   ed  = (const int*)d_in[9];
    float* out = (float*)d_out;

    const int E = in_sizes[7];

    __half *xh, *w1b, *w2b, *hb, *pz;
    float *ps1, *cwv;
    int *cnt, *part, *aux, *ptr, *wp, *csrc;
    cudaGetSymbolAddress((void**)&xh,   g_xh);
    cudaGetSymbolAddress((void**)&w1b,  g_w1);
    cudaGetSymbolAddress((void**)&w2b,  g_w2b);
    cudaGetSymbolAddress((void**)&hb,   g_h);
    cudaGetSymbolAddress((void**)&pz,   g_z);
    cudaGetSymbolAddress((void**)&ps1,  g_s1);
    cudaGetSymbolAddress((void**)&cnt,  g_cnt);
    cudaGetSymbolAddress((void**)&part, g_part);
    cudaGetSymbolAddress((void**)&aux,  g_aux);
    cudaGetSymbolAddress((void**)&ptr,  g_ptr);
    cudaGetSymbolAddress((void**)&wp,   g_wp);
    cudaGetSymbolAddress((void**)&csrc, g_csrc);
    cudaGetSymbolAddress((void**)&cwv,  g_cw);

    cudaFuncSetAttribute(gemm_hmma_kernel,
                         cudaFuncAttributeMaxDynamicSharedMemorySize, 2 * STG);

    static cudaStream_t s2 = nullptr, s3 = nullptr, sg = nullptr;
    static cudaEvent_t ev_fork = nullptr, ev_csr = nullptr,
                       ev_w1 = nullptr, ev_w2 = nullptr, ev_g1 = nullptr;
    static cudaEvent_t ev_sx[NSLICE] = {nullptr, nullptr, nullptr, nullptr};
    if (s2 == nullptr) {
        cudaStreamCreate(&s2);
        cudaStreamCreate(&s3);
        cudaStreamCreate(&sg);
        cudaEventCreateWithFlags(&ev_fork, cudaEventDisableTiming);
        cudaEventCreateWithFlags(&ev_csr,  cudaEventDisableTiming);
        cudaEventCreateWithFlags(&ev_w1,   cudaEventDisableTiming);
        cudaEventCreateWithFlags(&ev_w2,   cudaEventDisableTiming);
        cudaEventCreateWithFlags(&ev_g1,   cudaEventDisableTiming);
        for (int i = 0; i < NSLICE; i++)
            cudaEventCreateWithFlags(&ev_sx[i], cudaEventDisableTiming);
    }

    // M-slice boundaries (y-blocks; 391 total)
    const int YB = NNP / 128;                 // 391
    const int yb_per = (YB + NSLICE - 1) / NSLICE;   // 98

    // ---- fork ----
    cudaEventRecord(ev_fork, 0);
    cudaStreamWaitEvent(s2, ev_fork, 0);
    cudaStreamWaitEvent(s3, ev_fork, 0);
    cudaStreamWaitEvent(sg, ev_fork, 0);

    // -- s3: weight prep --
    {
        dim3 g1((INDP + 31) / 32, (HSTR + 31) / 32);
        prep_w_kernel<<<g1, 256, 0, s3>>>(w1, w1b, IND, HID, INDP, HSTR);
    }
    cudaEventRecord(ev_w1, s3);
    {
        dim3 g2((HSTR + 31) / 32, (HSTR + 31) / 32);
        prep_w_kernel<<<g2, 256, 0, s3>>>(w2, w2b, HID, HID, HSTR, HSTR);
    }
    cudaEventRecord(ev_w2, s3);

    // -- s2: CSR build --
    cnt_zero_kernel<<<(NNP + 255) / 256, 256, 0, s2>>>(cnt);
    hist_kernel<<<(E + 255) / 256, 256, 0, s2>>>(ed, cnt, E);
    {
        int nb = (NN + 255) / 256;   // 196
        scan1_kernel<<<nb, 256, 0, s2>>>(cnt, part, aux, NN);
        scan2_kernel<<<1, 256, 0, s2>>>(aux, nb);
        scan3_kernel<<<nb, 256, 0, s2>>>(part, aux, ptr, wp, NN, E);
    }
    fill_kernel<<<(E + 255) / 256, 256, 0, s2>>>(es, ed, ew, wp, csrc, cwv, E);
    cudaEventRecord(ev_csr, s2);

    // -- main: split_x slices; sg: GEMM1 slices gated per-slice --
    cudaStreamWaitEvent(sg, ev_w1, 0);
    for (int sl = 0; sl < NSLICE; sl++) {
        int y0 = sl * yb_per;
        int ny = (sl == NSLICE - 1) ? (YB - y0) : yb_per;
        if (ny <= 0) break;
        int roff = y0 * 128;
        int rcnt = roff < NN ? ((roff + ny * 128 > NN) ? (NN - roff) : ny * 128) : 0;
        if (rcnt > 0) {
            int total = rcnt * XCHUNKS;
            split_x_kernel<<<(total + 255) / 256, 256>>>(x, xh, roff, rcnt);
        }
        cudaEventRecord(ev_sx[sl], 0);
        cudaStreamWaitEvent(sg, ev_sx[sl], 0);
        dim3 gg(HSTR / 128, ny);
        gemm_hmma_kernel<<<gg, 256, 2 * STG, sg>>>(xh, INDP, w1b, INDP,
                                                   pz, HSTR, INDP / 64, y0);
    }
    cudaEventRecord(ev_g1, sg);

    // -- join: GEMM1 + CSR + w2 must be complete --
    cudaStreamWaitEvent(0, ev_g1, 0);
    cudaStreamWaitEvent(0, ev_csr, 0);
    cudaStreamWaitEvent(0, ev_w2, 0);

    // ---- Layer 1 aggregate ----
    gather_kernel<<<NN, 128>>>(pz, ptr, csrc, cwv, b1, hb);

    // ---- Layer 2 GEMM + fused aggregate/projection ----
    {
        dim3 gg(HSTR / 128, YB);
        gemm_hmma_kernel<<<gg, 256, 2 * STG>>>(hb, HSTR, w2b, HSTR,
                                               pz, HSTR, HSTR / 64, 0);
    }
    gather_proj_kernel<<<NN, 128>>>(pz, ptr, csrc, cwv, b2, w3, ps1);

    // ---- Layer 3 aggregate + log_softmax ----
    final_kernel<<<(NN + 7) / 8, 256>>>(ps1, ptr, csrc, cwv, b3, out, NN);

    (void)n_in; (void)out_size;
}

// round 17
// speedup vs baseline: 1.0866x; 1.0866x over previous
#include <cuda_runtime.h>
#include <cuda_fp16.h>
#include <math.h>
#include <stdint.h>

// ===========================================================================
// Problem constants (fixed shapes)
// ===========================================================================
#define NN     50000          // nodes
#define NNP    50048          // padded to 128
#define IND    3703           // input dim
#define INDP   3712           // padded to 64
#define HID    500
#define HSTR   512            // padded hidden
#define EMAX   1000000

// ===========================================================================
// Device scratch (static globals; no dynamic allocation).
// Pad rows/cols rely on static zero-init where noted; z pad cols are zero
// because weight pad rows are zero.
// ===========================================================================
__device__ __half g_xh[(size_t)NNP * INDP];
__device__ __half g_w1[HSTR * INDP];
__device__ __half g_w2b[HSTR * HSTR];
__device__ __half g_h[(size_t)NNP * HSTR];
__device__ __half g_z[(size_t)NNP * HSTR];   // GEMM output (fp16)
__device__ float g_s1[(size_t)NNP * 8];      // layer-3 per-node logits (pre-agg)

__device__ int   g_cnt[NNP];
__device__ int   g_part[NNP];
__device__ int   g_aux[256];
__device__ int   g_ptr[NN + 1];
__device__ int   g_wp[NNP];
__device__ int   g_csrc[EMAX];
__device__ float g_cw[EMAX];

// ===========================================================================
// Helpers
// ===========================================================================
__device__ __forceinline__ uint32_t smem_to_u32(const void* p) {
    uint32_t a;
    asm("{ .reg .u64 t; cvta.to.shared.u64 t, %1; cvt.u32.u64 %0, t; }"
        : "=r"(a) : "l"(p));
    return a;
}
__device__ __forceinline__ void ldsm4(uint32_t& r0, uint32_t& r1,
                                      uint32_t& r2, uint32_t& r3, uint32_t addr) {
    asm volatile("ldmatrix.sync.aligned.m8n8.x4.shared.b16 {%0,%1,%2,%3}, [%4];"
        : "=r"(r0), "=r"(r1), "=r"(r2), "=r"(r3) : "r"(addr));
}
__device__ __forceinline__ void mma16816(float* c, const uint32_t* a,
                                         uint32_t b0, uint32_t b1) {
    asm volatile("mma.sync.aligned.m16n8k16.row.col.f32.f16.f16.f32 "
        "{%0,%1,%2,%3}, {%4,%5,%6,%7}, {%8,%9}, {%0,%1,%2,%3};"
        : "+f"(c[0]), "+f"(c[1]), "+f"(c[2]), "+f"(c[3])
        : "r"(a[0]), "r"(a[1]), "r"(a[2]), "r"(a[3]), "r"(b0), "r"(b1));
}
__device__ __forceinline__ void cp16(uint32_t soff, const void* g) {
    asm volatile("cp.async.cg.shared.global [%0], [%1], 16;" :: "r"(soff), "l"(g));
}
__device__ __forceinline__ uint32_t pkh(__half a, __half b) {
    return (uint32_t)__half_as_ushort(a) | ((uint32_t)__half_as_ushort(b) << 16);
}

// ===========================================================================
// X -> fp16 (rows 0..NN-1; pad rows stay zero)
// ===========================================================================
#define XCHUNKS (INDP / 8)   // 464
__global__ __launch_bounds__(256)
void split_x_kernel(const float* __restrict__ x, __half* __restrict__ xh)
{
    int idx = blockIdx.x * 256 + threadIdx.x;
    int total = NN * XCHUNKS;
    if (idx >= total) return;
    int row = idx / XCHUNKS;
    int cb  = (idx - row * XCHUNKS) * 8;
    const float* px = x + (size_t)row * IND;
    __half hh[8];
#pragma unroll
    for (int j = 0; j < 8; j++) {
        int c = cb + j;
        hh[j] = __float2half_rn((c < IND) ? px[c] : 0.f);
    }
    size_t off = (size_t)row * INDP + cb;
    uint4 uh;
    uh.x = pkh(hh[0], hh[1]); uh.y = pkh(hh[2], hh[3]);
    uh.z = pkh(hh[4], hh[5]); uh.w = pkh(hh[6], hh[7]);
    *(uint4*)(xh + off) = uh;
}

// ===========================================================================
// Weight prep (coalesced transpose): w [K x N] fp32 -> fp16 [NP][KP]
// ===========================================================================
__global__ __launch_bounds__(256)
void prep_w_kernel(const float* __restrict__ w, __half* __restrict__ dh,
                   int K, int N, int KP, int NP)
{
    __shared__ float t[32][33];
    int kb = blockIdx.x * 32;
    int nb = blockIdx.y * 32;
    int tx = threadIdx.x & 31;
    int ty = threadIdx.x >> 5;     // 0..7
#pragma unroll
    for (int i = ty; i < 32; i += 8) {
        int k = kb + i, n = nb + tx;
        t[i][tx] = (k < K && n < N) ? w[(size_t)k * N + n] : 0.f;
    }
    __syncthreads();
#pragma unroll
    for (int i = ty; i < 32; i += 8) {
        int n = nb + i, k = kb + tx;
        if (n < NP && k < KP)
            dh[(size_t)n * KP + k] = __float2half_rn(t[tx][i]);
    }
}

// ===========================================================================
// CSR build
// ===========================================================================
__global__ void cnt_zero_kernel(int* __restrict__ cnt) {
    int i = blockIdx.x * 256 + threadIdx.x;
    if (i < NNP) cnt[i] = 0;
}
__global__ void hist_kernel(const int* __restrict__ ed, int* __restrict__ cnt, int E) {
    int e = blockIdx.x * 256 + threadIdx.x;
    if (e < E) atomicAdd(&cnt[ed[e]], 1);
}
__global__ void scan1_kernel(const int* __restrict__ cnt, int* __restrict__ part,
                             int* __restrict__ aux, int n)
{
    __shared__ int s[256];
    int tid = threadIdx.x;
    int g = blockIdx.x * 256 + tid;
    int v = (g < n) ? cnt[g] : 0;
    s[tid] = v;
    __syncthreads();
#pragma unroll
    for (int o = 1; o < 256; o <<= 1) {
        int t = (tid >= o) ? s[tid - o] : 0;
        __syncthreads();
        s[tid] += t;
        __syncthreads();
    }
    if (g < n) part[g] = s[tid] - v;
    if (tid == 255) aux[blockIdx.x] = s[tid];
}
__global__ void scan2_kernel(int* __restrict__ aux, int nb)
{
    __shared__ int s[256];
    int tid = threadIdx.x;
    int v = (tid < nb) ? aux[tid] : 0;
    s[tid] = v;
    __syncthreads();
#pragma unroll
    for (int o = 1; o < 256; o <<= 1) {
        int t = (tid >= o) ? s[tid - o] : 0;
        __syncthreads();
        s[tid] += t;
        __syncthreads();
    }
    if (tid < nb) aux[tid] = s[tid] - v;   // exclusive
}
__global__ void scan3_kernel(const int* __restrict__ part, const int* __restrict__ aux,
                             int* __restrict__ ptr, int* __restrict__ wp, int n, int E)
{
    int g = blockIdx.x * 256 + threadIdx.x;
    if (g < n) {
        int v = part[g] + aux[g >> 8];
        ptr[g] = v;
        wp[g] = v;
    }
    if (g == 0) ptr[n] = E;
}
__global__ void fill_kernel(const int* __restrict__ es, const int* __restrict__ ed,
                            const float* __restrict__ ew, int* __restrict__ wp,
                            int* __restrict__ csrc, float* __restrict__ cw, int E)
{
    int e = blockIdx.x * 256 + threadIdx.x;
    if (e >= E) return;
    int d = ed[e];
    int p = atomicAdd(&wp[d], 1);
    csrc[p] = es[e];
    cw[p] = ew[e];
}

// ===========================================================================
// HMMA GEMM (R11-proven, 571us): C[M x 512] = A[M x K] @ B^T[512 x K],
// fp16 operands, fp32 accum. BK=64 per stage as TWO BK=32 tile-pairs
// [A0|A1|B0|B1]; 2-stage cp.async pipeline; 256 threads, warp tile 64x32.
// ===========================================================================
#define STG 32768   // bytes per stage: 4 sub-tiles x 8KB

__global__ __launch_bounds__(256)
void gemm_hmma_kernel(const __half* __restrict__ Ah, int lda,
                      const __half* __restrict__ Bh, int ldb,
                      __half* __restrict__ C, int ldc, int nkc)   // nkc: 64-wide chunks
{
    extern __shared__ char smem[];
    const uint32_t sb = smem_to_u32(smem);
    const int tid  = threadIdx.x;
    const int lane = tid & 31;
    const int wid  = tid >> 5;
    const int m0 = blockIdx.y * 128;
    const int n0 = blockIdx.x * 128;
    const int wm = (wid >> 2) * 64;
    const int wn = (wid & 3) * 32;

    float acc[4][4][4];
#pragma unroll
    for (int i = 0; i < 4; i++)
#pragma unroll
        for (int j = 0; j < 4; j++)
#pragma unroll
            for (int q = 0; q < 4; q++) acc[i][j][q] = 0.f;

    auto load_stage = [&](int kc, int s) {
        int kkbase = kc * 64;
#pragma unroll
        for (int j = 0; j < 8; j++) {
            int id  = tid + j * 256;          // 0..2047
            int p   = id >> 10;               // 0..1 : which 32-col half
            int sub = id & 1023;
            int tile = sub >> 9;              // 0=A, 1=B
            int r = (sub >> 2) & 127;
            int c = sub & 3;
            uint32_t soff = sb + s * STG + tile * 16384 + p * 8192 + r * 64
                          + ((c ^ ((r >> 1) & 3)) << 4);
            int kk = kkbase + p * 32;
            const __half* g;
            if (tile == 0) g = Ah + (size_t)(m0 + r) * lda + kk + c * 8;
            else           g = Bh + (size_t)(n0 + r) * ldb + kk + c * 8;
            cp16(soff, g);
        }
        asm volatile("cp.async.commit_group;");
    };

    load_stage(0, 0);

    for (int kc = 0; kc < nkc; kc++) {
        int s = kc & 1;
        if (kc + 1 < nkc) {
            load_stage(kc + 1, s ^ 1);
            asm volatile("cp.async.wait_group 1;");
        } else {
            asm volatile("cp.async.wait_group 0;");
        }
        __syncthreads();

#pragma unroll
        for (int p = 0; p < 2; p++) {
            uint32_t tAh = sb + s * STG + p * 8192;
            uint32_t tBh = sb + s * STG + 16384 + p * 8192;

#pragma unroll
            for (int kh = 0; kh < 2; kh++) {
                uint32_t ah[4][4], bh[2][4];
                const int rlo = lane & 15;
                const int q   = 2 * kh + (lane >> 4);
#pragma unroll
                for (int i = 0; i < 4; i++) {
                    int r = wm + i * 16 + rlo;
                    uint32_t off = r * 64 + ((q ^ ((r >> 1) & 3)) << 4);
                    ldsm4(ah[i][0], ah[i][1], ah[i][2], ah[i][3], tAh + off);
                }
#pragma unroll
                for (int j = 0; j < 2; j++) {
                    int r = wn + j * 16 + rlo;
                    uint32_t off = r * 64 + ((q ^ ((r >> 1) & 3)) << 4);
                    ldsm4(bh[j][0], bh[j][1], bh[j][2], bh[j][3], tBh + off);
                }
#pragma unroll
                for (int i = 0; i < 4; i++) {
#pragma unroll
                    for (int jj = 0; jj < 4; jj++) {
                        uint32_t b0 = bh[jj >> 1][jj & 1];
                        uint32_t b1 = bh[jj >> 1][(jj & 1) + 2];
                        mma16816(acc[i][jj], ah[i], b0, b1);
                    }
                }
            }
        }
        __syncthreads();
    }

    // epilogue: fp32 acc -> fp16 stores
#pragma unroll
    for (int i = 0; i < 4; i++) {
        int row = m0 + wm + i * 16 + (lane >> 2);
#pragma unroll
        for (int jj = 0; jj < 4; jj++) {
            int col = n0 + wn + jj * 8 + 2 * (lane & 3);
            __half2 v0 = __floats2half2_rn(acc[i][jj][0], acc[i][jj][1]);
            __half2 v1 = __floats2half2_rn(acc[i][jj][2], acc[i][jj][3]);
            *(__half2*)(C + (size_t)row * ldc + col) = v0;
            *(__half2*)(C + (size_t)(row + 8) * ldc + col) = v1;
        }
    }
}

// ===========================================================================
// Layer-1 CSR gather, half2 loads: thread t owns col pairs {2t, 2t+1} and
// {256+2t, 257+2t}. One 4B load per pair per edge (halves LDG count vs
// scalar), 128B fully-coalesced per warp, all 128 threads active,
// same 8-accumulator footprint as the proven R9 2-way edge unroll.
// z pad cols (>=500) are exactly zero; bias reads guarded.
// ===========================================================================
__global__ __launch_bounds__(128)
void gather_kernel(const __half* __restrict__ src, const int* __restrict__ ptr,
                   const int* __restrict__ cs, const float* __restrict__ cw,
                   const float* __restrict__ bias,
                   __half* __restrict__ oh)
{
    int node = blockIdx.x;
    int t = threadIdx.x;
    int beg = ptr[node], end = ptr[node + 1];
    const int c0 = 2 * t;          // 0..254
    const int c1 = 256 + 2 * t;    // 256..510
    float a0x = 0.f, a0y = 0.f, a1x = 0.f, a1y = 0.f;
    float e0x = 0.f, e0y = 0.f, e1x = 0.f, e1y = 0.f;
    int i = beg;
    for (; i + 1 < end; i += 2) {
        int sA = cs[i],   sB = cs[i + 1];
        float wA = cw[i], wB = cw[i + 1];
        const __half* pA = src + (size_t)sA * HSTR;
        const __half* pB = src + (size_t)sB * HSTR;
        float2 fA0 = __half22float2(*(const __half2*)(pA + c0));
        float2 fA1 = __half22float2(*(const __half2*)(pA + c1));
        float2 fB0 = __half22float2(*(const __half2*)(pB + c0));
        float2 fB1 = __half22float2(*(const __half2*)(pB + c1));
        a0x = fmaf(wA, fA0.x, a0x);  a0y = fmaf(wA, fA0.y, a0y);
        a1x = fmaf(wA, fA1.x, a1x);  a1y = fmaf(wA, fA1.y, a1y);
        e0x = fmaf(wB, fB0.x, e0x);  e0y = fmaf(wB, fB0.y, e0y);
        e1x = fmaf(wB, fB1.x, e1x);  e1y = fmaf(wB, fB1.y, e1y);
    }
    if (i < end) {
        int s = cs[i]; float w = cw[i];
        const __half* ps = src + (size_t)s * HSTR;
        float2 f0 = __half22float2(*(const __half2*)(ps + c0));
        float2 f1 = __half22float2(*(const __half2*)(ps + c1));
        a0x = fmaf(w, f0.x, a0x);  a0y = fmaf(w, f0.y, a0y);
        a1x = fmaf(w, f1.x, a1x);  a1y = fmaf(w, f1.y, a1y);
    }
    a0x += e0x; a0y += e0y; a1x += e1x; a1y += e1y;

    float2 b0 = *(const float2*)(bias + c0);           // c0+1 <= 255 < HID
    float b1x = (c1     < HID) ? bias[c1]     : 0.f;
    float b1y = (c1 + 1 < HID) ? bias[c1 + 1] : 0.f;
    float v0 = fmaxf(a0x + b0.x, 0.f);
    float v1 = fmaxf(a0y + b0.y, 0.f);
    float v2 = fmaxf(a1x + b1x, 0.f);
    float v3 = fmaxf(a1y + b1y, 0.f);
    size_t base = (size_t)node * HSTR;
    *(__half2*)(oh + base + c0) = __floats2half2_rn(v0, v1);
    *(__half2*)(oh + base + c1) = __floats2half2_rn(v2, v3);
}

// ===========================================================================
// Layer-2 gather fused with W3 projection (same half2-pair scheme).
// h2 pad cols are provably zero (z pad zero, bias guard) -> w3 reads guarded.
// ===========================================================================
__global__ __launch_bounds__(128)
void gather_proj_kernel(const __half* __restrict__ src, const int* __restrict__ ptr,
                        const int* __restrict__ cs, const float* __restrict__ cw,
                        const float* __restrict__ bias,
                        const float* __restrict__ w3,
                        float* __restrict__ s1)
{
    __shared__ float red[6][128];
    int node = blockIdx.x;
    int t = threadIdx.x;
    int beg = ptr[node], end = ptr[node + 1];
    const int c0 = 2 * t;          // 0..254
    const int c1 = 256 + 2 * t;    // 256..510
    float a0x = 0.f, a0y = 0.f, a1x = 0.f, a1y = 0.f;
    float e0x = 0.f, e0y = 0.f, e1x = 0.f, e1y = 0.f;
    int i = beg;
    for (; i + 1 < end; i += 2) {
        int sA = cs[i],   sB = cs[i + 1];
        float wA = cw[i], wB = cw[i + 1];
        const __half* pA = src + (size_t)sA * HSTR;
        const __half* pB = src + (size_t)sB * HSTR;
        float2 fA0 = __half22float2(*(const __half2*)(pA + c0));
        float2 fA1 = __half22float2(*(const __half2*)(pA + c1));
        float2 fB0 = __half22float2(*(const __half2*)(pB + c0));
        float2 fB1 = __half22float2(*(const __half2*)(pB + c1));
        a0x = fmaf(wA, fA0.x, a0x);  a0y = fmaf(wA, fA0.y, a0y);
        a1x = fmaf(wA, fA1.x, a1x);  a1y = fmaf(wA, fA1.y, a1y);
        e0x = fmaf(wB, fB0.x, e0x);  e0y = fmaf(wB, fB0.y, e0y);
        e1x = fmaf(wB, fB1.x, e1x);  e1y = fmaf(wB, fB1.y, e1y);
    }
    if (i < end) {
        int s = cs[i]; float w = cw[i];
        const __half* ps = src + (size_t)s * HSTR;
        float2 f0 = __half22float2(*(const __half2*)(ps + c0));
        float2 f1 = __half22float2(*(const __half2*)(ps + c1));
        a0x = fmaf(w, f0.x, a0x);  a0y = fmaf(w, f0.y, a0y);
        a1x = fmaf(w, f1.x, a1x);  a1y = fmaf(w, f1.y, a1y);
    }
    a0x += e0x; a0y += e0y; a1x += e1x; a1y += e1y;

    float2 b0 = *(const float2*)(bias + c0);
    float b1x = (c1     < HID) ? bias[c1]     : 0.f;
    float b1y = (c1 + 1 < HID) ? bias[c1 + 1] : 0.f;
    float v0 = fmaxf(a0x + b0.x, 0.f);
    float v1 = fmaxf(a0y + b0.y, 0.f);
    float v2 = (c1     < HID) ? fmaxf(a1x + b1x, 0.f) : 0.f;
    float v3 = (c1 + 1 < HID) ? fmaxf(a1y + b1y, 0.f) : 0.f;

    float p[6] = {0.f, 0.f, 0.f, 0.f, 0.f, 0.f};
    const float* r0 = w3 + (size_t)c0 * 6;
    const float* r1 = w3 + (size_t)(c0 + 1) * 6;
#pragma unroll
    for (int j = 0; j < 6; j++) {
        float s = v0 * __ldg(&r0[j]) + v1 * __ldg(&r1[j]);
        if (c1     < HID) s += v2 * __ldg(&w3[(size_t)c1 * 6 + j]);
        if (c1 + 1 < HID) s += v3 * __ldg(&w3[(size_t)(c1 + 1) * 6 + j]);
        p[j] = s;
    }
#pragma unroll
    for (int j = 0; j < 6; j++) red[j][t] = p[j];
    __syncthreads();
#pragma unroll
    for (int s = 64; s >= 1; s >>= 1) {
        if (t < s) {
#pragma unroll
            for (int j = 0; j < 6; j++) red[j][t] += red[j][t + s];
        }
        __syncthreads();
    }
    if (t < 6) s1[(size_t)node * 8 + t] = red[t][0];
}

// ===========================================================================
// Final fused: aggregate (CSR) + b3 + log_softmax, warp per node
// ===========================================================================
__global__ void final_kernel(const float* __restrict__ s1, const int* __restrict__ ptr,
                             const int* __restrict__ cs, const float* __restrict__ cw,
                             const float* __restrict__ b3, float* __restrict__ out, int M)
{
    int node = (blockIdx.x * blockDim.x + threadIdx.x) >> 5;
    int lane = threadIdx.x & 31;
    if (node >= M) return;
    int beg = ptr[node], end = ptr[node + 1];
    float a[6] = {0.f, 0.f, 0.f, 0.f, 0.f, 0.f};
    for (int i = beg + lane; i < end; i += 32) {
        int s = cs[i];
        float w = cw[i];
        const float* ps = s1 + (size_t)s * 8;
#pragma unroll
        for (int j = 0; j < 6; j++) a[j] = fmaf(w, ps[j], a[j]);
    }
#pragma unroll
    for (int j = 0; j < 6; j++)
#pragma unroll
        for (int off = 16; off > 0; off >>= 1)
            a[j] += __shfl_xor_sync(0xffffffffu, a[j], off);
    if (lane == 0) {
        float v[6];
#pragma unroll
        for (int j = 0; j < 6; j++) v[j] = a[j] + b3[j];
        float m = v[0];
#pragma unroll
        for (int j = 1; j < 6; j++) m = fmaxf(m, v[j]);
        float s = 0.f;
#pragma unroll
        for (int j = 0; j < 6; j++) s += __expf(v[j] - m);
        float l = logf(s) + m;
        float* po = out + (size_t)node * 6;
#pragma unroll
        for (int j = 0; j < 6; j++) po[j] = v[j] - l;
    }
}

// ===========================================================================
// Launch (R14-proven 3-stream fork-join):
//   main: split_x -> (wait w1) GEMM1 -> (wait CSR+w2) gather1 -> GEMM2 -> ...
//   s3:   prep_w1 (ev_w1) -> prep_w2
//   s2:   CSR build chain
// Streams/events cached; identical deterministic work each call.
// ===========================================================================
extern "C" void kernel_launch(void* const* d_in, const int* in_sizes, int n_in,
                              void* d_out, int out_size)
{
    const float* x   = (const float*)d_in[0];
    const float* w1  = (const float*)d_in[1];
    const float* b1  = (const float*)d_in[2];
    const float* w2  = (const float*)d_in[3];
    const float* b2  = (const float*)d_in[4];
    const float* w3  = (const float*)d_in[5];
    const float* b3  = (const float*)d_in[6];
    const float* ew  = (const float*)d_in[7];
    const int*   es  = (const int*)d_in[8];
    const int*   ed  = (const int*)d_in[9];
    float* out = (float*)d_out;

    const int E = in_sizes[7];

    __half *xh, *w1b, *w2b, *hb, *pz;
    float *ps1, *cwv;
    int *cnt, *part, *aux, *ptr, *wp, *csrc;
    cudaGetSymbolAddress((void**)&xh,   g_xh);
    cudaGetSymbolAddress((void**)&w1b,  g_w1);
    cudaGetSymbolAddress((void**)&w2b,  g_w2b);
    cudaGetSymbolAddress((void**)&hb,   g_h);
    cudaGetSymbolAddress((void**)&pz,   g_z);
    cudaGetSymbolAddress((void**)&ps1,  g_s1);
    cudaGetSymbolAddress((void**)&cnt,  g_cnt);
    cudaGetSymbolAddress((void**)&part, g_part);
    cudaGetSymbolAddress((void**)&aux,  g_aux);
    cudaGetSymbolAddress((void**)&ptr,  g_ptr);
    cudaGetSymbolAddress((void**)&wp,   g_wp);
    cudaGetSymbolAddress((void**)&csrc, g_csrc);
    cudaGetSymbolAddress((void**)&cwv,  g_cw);

    cudaFuncSetAttribute(gemm_hmma_kernel,
                         cudaFuncAttributeMaxDynamicSharedMemorySize, 2 * STG);

    static cudaStream_t s2 = nullptr, s3 = nullptr;
    static cudaEvent_t ev_fork = nullptr, ev_csr = nullptr, ev_w1 = nullptr, ev_w2 = nullptr;
    if (s2 == nullptr) {
        cudaStreamCreate(&s2);
        cudaStreamCreate(&s3);
        cudaEventCreateWithFlags(&ev_fork, cudaEventDisableTiming);
        cudaEventCreateWithFlags(&ev_csr,  cudaEventDisableTiming);
        cudaEventCreateWithFlags(&ev_w1,   cudaEventDisableTiming);
        cudaEventCreateWithFlags(&ev_w2,   cudaEventDisableTiming);
    }

    dim3 ggrid(HSTR / 128, NNP / 128);   // (4, 391), N fastest for A L2 reuse

    // ---- fork ----
    cudaEventRecord(ev_fork, 0);
    cudaStreamWaitEvent(s2, ev_fork, 0);
    cudaStreamWaitEvent(s3, ev_fork, 0);

    // -- s3: weight prep path --
    {
        dim3 g1((INDP + 31) / 32, (HSTR + 31) / 32);
        prep_w_kernel<<<g1, 256, 0, s3>>>(w1, w1b, IND, HID, INDP, HSTR);
    }
    cudaEventRecord(ev_w1, s3);
    {
        dim3 g2((HSTR + 31) / 32, (HSTR + 31) / 32);
        prep_w_kernel<<<g2, 256, 0, s3>>>(w2, w2b, HID, HID, HSTR, HSTR);
    }
    cudaEventRecord(ev_w2, s3);

    // -- s2: CSR build path --
    cnt_zero_kernel<<<(NNP + 255) / 256, 256, 0, s2>>>(cnt);
    hist_kernel<<<(E + 255) / 256, 256, 0, s2>>>(ed, cnt, E);
    {
        int nb = (NN + 255) / 256;   // 196
        scan1_kernel<<<nb, 256, 0, s2>>>(cnt, part, aux, NN);
        scan2_kernel<<<1, 256, 0, s2>>>(aux, nb);
        scan3_kernel<<<nb, 256, 0, s2>>>(part, aux, ptr, wp, NN, E);
    }
    fill_kernel<<<(E + 255) / 256, 256, 0, s2>>>(es, ed, ew, wp, csrc, cwv, E);
    cudaEventRecord(ev_csr, s2);

    // -- main: X conversion, then Layer-1 GEMM (needs w1b) --
    {
        int total = NN * XCHUNKS;
        split_x_kernel<<<(total + 255) / 256, 256>>>(x, xh);
    }
    cudaStreamWaitEvent(0, ev_w1, 0);
    gemm_hmma_kernel<<<ggrid, 256, 2 * STG>>>(xh, INDP, w1b, INDP,
                                              pz, HSTR, INDP / 64);

    // -- join: CSR (ptr/csrc/cw) needed by gather, w2b by GEMM2 --
    cudaStreamWaitEvent(0, ev_csr, 0);
    cudaStreamWaitEvent(0, ev_w2, 0);

    // ---- Layer 1 aggregate ----
    gather_kernel<<<NN, 128>>>(pz, ptr, csrc, cwv, b1, hb);

    // ---- Layer 2 GEMM + fused aggregate/projection ----
    gemm_hmma_kernel<<<ggrid, 256, 2 * STG>>>(hb, HSTR, w2b, HSTR,
                                              pz, HSTR, HSTR / 64);
    gather_proj_kernel<<<NN, 128>>>(pz, ptr, csrc, cwv, b2, w3, ps1);

    // ---- Layer 3 aggregate + log_softmax ----
    final_kernel<<<(NN + 7) / 8, 256>>>(ps1, ptr, csrc, cwv, b3, out, NN);

    (void)n_in; (void)out_size;
}